// round 7
// baseline (speedup 1.0000x reference)
#include <cuda_runtime.h>

#define BATCH 256
#define EDIM  128
#define HDIM  256
#define VOCAB 32000
#define G4H   1024   // 4*H
#define ODIM  2
#define NCTA  128    // persistent grid (<=148 SMs -> wave-1 co-resident)

// ---------------- scratch (device globals; no runtime allocation) -----------
__device__ float    g_proj[(size_t)VOCAB * G4H];  // emb@w_ih^T + bias  (131 MB)
__device__ float    g_h[2][HDIM][BATCH];          // double-buffered h, TRANSPOSED [j][b]
__device__ float    g_lasth[BATCH][HDIM];         // last valid h (for decode)
__device__ unsigned g_bar_gen;                    // grid-barrier generation (monotonic)
__device__ unsigned g_bar_count;                  // grid-barrier arrival counter

// ---------------- grid barrier (monotonic target; replay-safe) --------------
__device__ __forceinline__ void grid_barrier(unsigned target) {
    __syncthreads();
    if (threadIdx.x == 0) {
        __threadfence();                                   // release my h-writes
        unsigned arrived = atomicAdd(&g_bar_count, 1u);
        if (arrived == NCTA - 1) {
            g_bar_count = 0u;
            __threadfence();
            *(volatile unsigned*)&g_bar_gen = target;      // release all
        } else {
            while ((int)(*(volatile unsigned*)&g_bar_gen - target) < 0) { }
            __threadfence();                               // acquire
        }
    }
    __syncthreads();
}

// ---------------- kernel 1: proj_table = emb @ w_ih^T + (b_ih + b_hh) -------
// 64 vocab-rows x 64 gate-cols per CTA, K chunked by 64.  grid = 500*16
__global__ void __launch_bounds__(256) prep_proj_kernel(
    const float* __restrict__ emb, const float* __restrict__ w_ih,
    const float* __restrict__ b_ih, const float* __restrict__ b_hh)
{
    __shared__ float sA[64][65];   // sA[k][v]
    __shared__ float sW[64][65];   // sW[k][c]
    const int cb = blockIdx.x & 15, vb = blockIdx.x >> 4;
    const int vbase = vb * 64, cbase = cb * 64;
    const int tid = threadIdx.x;
    const int c0 = (tid & 15) * 4, v0 = (tid >> 4) * 4;

    float acc[4][4];
#pragma unroll
    for (int i = 0; i < 4; i++)
#pragma unroll
        for (int j = 0; j < 4; j++) acc[i][j] = 0.0f;

    for (int kc = 0; kc < EDIM; kc += 64) {
#pragma unroll
        for (int r = 0; r < 16; r++) {
            int idx = tid + r * 256;
            int row = idx >> 6, kk = idx & 63;
            sA[kk][row] = emb [(vbase + row) * EDIM + kc + kk];
            sW[kk][row] = w_ih[(cbase + row) * EDIM + kc + kk];
        }
        __syncthreads();
#pragma unroll 8
        for (int k = 0; k < 64; k++) {
            float a0 = sA[k][v0], a1 = sA[k][v0+1], a2 = sA[k][v0+2], a3 = sA[k][v0+3];
            float w0 = sW[k][c0], w1 = sW[k][c0+1], w2 = sW[k][c0+2], w3 = sW[k][c0+3];
            acc[0][0]+=a0*w0; acc[0][1]+=a0*w1; acc[0][2]+=a0*w2; acc[0][3]+=a0*w3;
            acc[1][0]+=a1*w0; acc[1][1]+=a1*w1; acc[1][2]+=a1*w2; acc[1][3]+=a1*w3;
            acc[2][0]+=a2*w0; acc[2][1]+=a2*w1; acc[2][2]+=a2*w2; acc[2][3]+=a2*w3;
            acc[3][0]+=a3*w0; acc[3][1]+=a3*w1; acc[3][2]+=a3*w2; acc[3][3]+=a3*w3;
        }
        __syncthreads();
    }
    float bias[4];
#pragma unroll
    for (int j = 0; j < 4; j++) bias[j] = b_ih[cbase + c0 + j] + b_hh[cbase + c0 + j];
#pragma unroll
    for (int i = 0; i < 4; i++) {
        float4 v = make_float4(acc[i][0]+bias[0], acc[i][1]+bias[1],
                               acc[i][2]+bias[2], acc[i][3]+bias[3]);
        *(float4*)&g_proj[(size_t)(vbase + v0 + i) * G4H + cbase + c0] = v;
    }
}

// ---------------- kernel 2: persistent LSTM recurrence ----------------------
// 128 CTAs = 2 batch tiles (128 b) x 64 col tiles (4 hidden units = 16 gate cols)
__global__ void __launch_bounds__(256) lstm_kernel(
    const int*   __restrict__ inp,      // [S, B] time-major
    const int*   __restrict__ lengths,  // [B]
    const float* __restrict__ h0,       // [1, B, H]
    const float* __restrict__ c0,       // [1, B, H]
    const float* __restrict__ w_hh,     // [4H, H]
    float*       __restrict__ out,      // decoded(512) | last_h(65536) | last_c(65536)
    int wstate)
{
    __shared__ float2   wS2[HDIM][8];   // (w_hh[col],w_hh[col+1]) per j,colpair  16KB
    __shared__ float    gS[128][17];    // gate staging [b_local][g*4+u]          8.7KB
    __shared__ int      lenS[128];
    __shared__ int      sMax;
    __shared__ unsigned sBase;

    const int tid  = threadIdx.x;
    const int cidx = blockIdx.x & 63;   // column tile
    const int bt   = blockIdx.x >> 6;   // batch tile
    const int b0   = bt * 128;
    const int hu0  = cidx * 4;

    if (tid == 0) { sMax = 0; sBase = *(volatile unsigned*)&g_bar_gen; }
    __syncthreads();
    atomicMax(&sMax, lengths[tid]);                 // tid covers full B=256
    if (tid < 128) lenS[tid] = lengths[b0 + tid];

    // w_hh slice: 16 gate cols x 256 j, stored as col-pairs
    for (int idx = tid; idx < HDIM * 16; idx += 256) {
        int j = idx >> 4, cc = idx & 15;
        int col = (cc >> 2) * HDIM + hu0 + (cc & 3);
        ((float*)&wS2[j][0])[cc] = w_hh[col * HDIM + j];
    }
    // init h buffer 0 (transposed) and c registers
    const int pb = tid & 127;           // this thread's pointwise batch row
    const int pu = tid >> 7;            // pointwise unit base (0 or 1); owns pu, pu+2
    float creg0 = c0[(b0 + pb) * HDIM + hu0 + pu];
    float creg1 = c0[(b0 + pb) * HDIM + hu0 + pu + 2];
    for (int p = tid; p < 512; p += 256) {
        int b = p & 127, u = p >> 7;
        g_h[0][hu0 + u][b0 + b] = h0[(b0 + b) * HDIM + hu0 + u];
    }
    __syncthreads();
    const int      maxlen = sMax;
    const unsigned base   = sBase;
    grid_barrier(base + 1);                          // h[0] visible everywhere

    const int cp  = tid & 7;                         // gate-col pair 2cp,2cp+1
    const int q   = tid >> 3;                        // 4 batch rows 4q..4q+3
    const int cc0 = 2 * cp;
    const int colpair = (cc0 >> 2) * HDIM + hu0 + (cc0 & 3);

    int cur = 0;
    for (int t = 0; t < maxlen; t++) {
        // x-part: gather precomputed projection rows (prefetched)
        float2 xp0, xp1, xp2, xp3;
        {
            const int* ip = &inp[t * BATCH + b0 + 4 * q];
            xp0 = *(const float2*)&g_proj[(size_t)__ldg(ip+0) * G4H + colpair];
            xp1 = *(const float2*)&g_proj[(size_t)__ldg(ip+1) * G4H + colpair];
            xp2 = *(const float2*)&g_proj[(size_t)__ldg(ip+2) * G4H + colpair];
            xp3 = *(const float2*)&g_proj[(size_t)__ldg(ip+3) * G4H + colpair];
        }
        // recurrent GEMM slice: gates += h @ w_hh^T
        float2 a0 = make_float2(0.f,0.f), a1 = a0, a2 = a0, a3 = a0;
        const float* hp = &g_h[cur][0][b0 + 4 * q];
#pragma unroll 4
        for (int j = 0; j < HDIM; j++) {
            float4 h4 = __ldcg((const float4*)(hp + j * BATCH));  // L2-only (fresh)
            float2 w2 = wS2[j][cp];
            a0.x += h4.x * w2.x; a0.y += h4.x * w2.y;
            a1.x += h4.y * w2.x; a1.y += h4.y * w2.y;
            a2.x += h4.z * w2.x; a2.y += h4.z * w2.y;
            a3.x += h4.w * w2.x; a3.y += h4.w * w2.y;
        }
        gS[4*q+0][cc0] = a0.x + xp0.x;  gS[4*q+0][cc0+1] = a0.y + xp0.y;
        gS[4*q+1][cc0] = a1.x + xp1.x;  gS[4*q+1][cc0+1] = a1.y + xp1.y;
        gS[4*q+2][cc0] = a2.x + xp2.x;  gS[4*q+2][cc0+1] = a2.y + xp2.y;
        gS[4*q+3][cc0] = a3.x + xp3.x;  gS[4*q+3][cc0+1] = a3.y + xp3.y;
        __syncthreads();

        // pointwise cell: this thread owns (pb, pu) and (pb, pu+2)
        const int nxt = cur ^ 1;
        const int lastt = lenS[pb] - 1;
#pragma unroll
        for (int r = 0; r < 2; r++) {
            int u = pu + 2 * r;
            float gi = gS[pb][u],     gf = gS[pb][4 + u];
            float gc = gS[pb][8 + u], go = gS[pb][12 + u];
            float si = 1.0f / (1.0f + __expf(-gi));
            float sf = 1.0f / (1.0f + __expf(-gf));
            float so = 1.0f / (1.0f + __expf(-go));
            float tg = tanhf(gc);
            float cn = sf * (r ? creg1 : creg0) + si * tg;
            float hn = so * tanhf(cn);
            if (r) creg1 = cn; else creg0 = cn;
            int gb = b0 + pb, jj = hu0 + u;
            g_h[nxt][jj][gb] = hn;
            if (t == lastt) {
                g_lasth[gb][jj] = hn;
                if (wstate) {
                    out[ODIM*BATCH + gb*HDIM + jj] = hn;                 // last_h
                    out[ODIM*BATCH + BATCH*HDIM + gb*HDIM + jj] = cn;    // last_c
                }
            }
        }
        grid_barrier(base + 2 + t);
        cur = nxt;
    }
}

// ---------------- kernel 3: decoded = sigmoid(last_h @ dec_w^T) -------------
__global__ void __launch_bounds__(256) decode_kernel(
    const float* __restrict__ dec_w, float* __restrict__ out)
{
    int w = (blockIdx.x * blockDim.x + threadIdx.x) >> 5;   // global warp id
    int lane = threadIdx.x & 31;
    if (w >= BATCH * ODIM) return;
    int b = w >> 1, o = w & 1;
    float s = 0.0f;
#pragma unroll
    for (int j = lane; j < HDIM; j += 32) s += g_lasth[b][j] * dec_w[o * HDIM + j];
#pragma unroll
    for (int off = 16; off; off >>= 1) s += __shfl_xor_sync(0xFFFFFFFFu, s, off);
    if (lane == 0) out[b * ODIM + o] = 1.0f / (1.0f + __expf(-s));
}

// ---------------- launcher --------------------------------------------------
extern "C" void kernel_launch(void* const* d_in, const int* in_sizes, int n_in,
                              void* d_out, int out_size) {
    const int*   inp     = (const int*)  d_in[0];
    const int*   lengths = (const int*)  d_in[1];
    const float* h0      = (const float*)d_in[2];
    const float* c0      = (const float*)d_in[3];
    const float* emb     = (const float*)d_in[4];
    const float* w_ih    = (const float*)d_in[5];
    const float* w_hh    = (const float*)d_in[6];
    const float* b_ih    = (const float*)d_in[7];
    const float* b_hh    = (const float*)d_in[8];
    const float* dec_w   = (const float*)d_in[9];
    float* out = (float*)d_out;
    int wstate = (out_size >= ODIM * BATCH + 2 * BATCH * HDIM) ? 1 : 0;

    prep_proj_kernel<<<500 * 16, 256>>>(emb, w_ih, b_ih, b_hh);
    lstm_kernel<<<NCTA, 256>>>(inp, lengths, h0, c0, w_hh, out, wstate);
    decode_kernel<<<64, 256>>>(dec_w, out);
}

// round 11
// speedup vs baseline: 3.6562x; 3.6562x over previous
#include <cuda_runtime.h>

#define BATCH 256
#define EDIM  128
#define HDIM  256
#define VOCAB 32000
#define G4H   1024   // 4*H
#define ODIM  2
#define NCTA  128    // persistent grid (<=148 SMs -> wave-1 co-resident)
#define DSMEM (65536 + 32768)   // hS double-buffer (2x32KB) + duplicated w_hh (32KB)

// ---------------- scratch (device globals; no runtime allocation) -----------
__device__ float    g_proj[(size_t)VOCAB * G4H];  // emb@w_ih^T + bias  (131 MB)
__device__ float    g_h[2][HDIM][BATCH];          // double-buffered h, TRANSPOSED [j][b]
__device__ float    g_lasth[BATCH][HDIM];         // last valid h (for decode)
__device__ unsigned g_bar_gen;                    // grid-barrier generation (monotonic)
__device__ unsigned g_bar_count;                  // grid-barrier arrival counter

// ---------------- small asm helpers -----------------------------------------
__device__ __forceinline__ void ffma2(unsigned long long& d,
                                      unsigned long long a, unsigned long long b) {
    asm("fma.rn.f32x2 %0, %1, %2, %0;" : "+l"(d) : "l"(a), "l"(b));
}
__device__ __forceinline__ float2 unpk(unsigned long long v) {
    float2 r; asm("mov.b64 {%0,%1}, %2;" : "=f"(r.x), "=f"(r.y) : "l"(v)); return r;
}
__device__ __forceinline__ void cpa16(unsigned dst, const void* src) {
    asm volatile("cp.async.cg.shared.global [%0], [%1], 16;" :: "r"(dst), "l"(src));
}

// ---------------- grid barrier (monotonic target; replay-safe) --------------
__device__ __forceinline__ void grid_barrier(unsigned target) {
    __syncthreads();
    if (threadIdx.x == 0) {
        __threadfence();                                   // release my h-writes to L2
        unsigned arrived = atomicAdd(&g_bar_count, 1u);
        if (arrived == NCTA - 1) {
            g_bar_count = 0u;
            __threadfence();
            *(volatile unsigned*)&g_bar_gen = target;      // release all
        } else {
            while ((int)(*(volatile unsigned*)&g_bar_gen - target) < 0) { }
            __threadfence();                               // acquire
        }
    }
    __syncthreads();
}

// ---------------- kernel 1: proj_table = emb @ w_ih^T + (b_ih + b_hh) -------
__global__ void __launch_bounds__(256) prep_proj_kernel(
    const float* __restrict__ emb, const float* __restrict__ w_ih,
    const float* __restrict__ b_ih, const float* __restrict__ b_hh)
{
    __shared__ float sA[64][65];   // sA[k][v]
    __shared__ float sW[64][65];   // sW[k][c]
    const int cb = blockIdx.x & 15, vb = blockIdx.x >> 4;
    const int vbase = vb * 64, cbase = cb * 64;
    const int tid = threadIdx.x;
    const int c0 = (tid & 15) * 4, v0 = (tid >> 4) * 4;

    float acc[4][4];
#pragma unroll
    for (int i = 0; i < 4; i++)
#pragma unroll
        for (int j = 0; j < 4; j++) acc[i][j] = 0.0f;

    for (int kc = 0; kc < EDIM; kc += 64) {
#pragma unroll
        for (int r = 0; r < 16; r++) {
            int idx = tid + r * 256;
            int row = idx >> 6, kk = idx & 63;
            sA[kk][row] = emb [(vbase + row) * EDIM + kc + kk];
            sW[kk][row] = w_ih[(cbase + row) * EDIM + kc + kk];
        }
        __syncthreads();
#pragma unroll 8
        for (int k = 0; k < 64; k++) {
            float a0 = sA[k][v0], a1 = sA[k][v0+1], a2 = sA[k][v0+2], a3 = sA[k][v0+3];
            float w0 = sW[k][c0], w1 = sW[k][c0+1], w2 = sW[k][c0+2], w3 = sW[k][c0+3];
            acc[0][0]+=a0*w0; acc[0][1]+=a0*w1; acc[0][2]+=a0*w2; acc[0][3]+=a0*w3;
            acc[1][0]+=a1*w0; acc[1][1]+=a1*w1; acc[1][2]+=a1*w2; acc[1][3]+=a1*w3;
            acc[2][0]+=a2*w0; acc[2][1]+=a2*w1; acc[2][2]+=a2*w2; acc[2][3]+=a2*w3;
            acc[3][0]+=a3*w0; acc[3][1]+=a3*w1; acc[3][2]+=a3*w2; acc[3][3]+=a3*w3;
        }
        __syncthreads();
    }
    float bias[4];
#pragma unroll
    for (int j = 0; j < 4; j++) bias[j] = b_ih[cbase + c0 + j] + b_hh[cbase + c0 + j];
#pragma unroll
    for (int i = 0; i < 4; i++) {
        float4 v = make_float4(acc[i][0]+bias[0], acc[i][1]+bias[1],
                               acc[i][2]+bias[2], acc[i][3]+bias[3]);
        *(float4*)&g_proj[(size_t)(vbase + v0 + i) * G4H + cbase + c0] = v;
    }
}

// ---------------- kernel 2: persistent LSTM recurrence ----------------------
// 128 CTAs = 2 batch tiles (128 b) x 64 col tiles (4 hidden units = 16 gate cols)
// cp.async double-buffered h staging + packed fma.rn.f32x2 inner loop.
__global__ void __launch_bounds__(256) lstm_kernel(
    const int*   __restrict__ inp,      // [S, B] time-major
    const int*   __restrict__ lengths,  // [B]
    const float* __restrict__ h0,       // [1, B, H]
    const float* __restrict__ c0,       // [1, B, H]
    const float* __restrict__ w_hh,     // [4H, H]
    float*       __restrict__ out,      // decoded(512) | last_h(65536) | last_c(65536)
    int wstate)
{
    extern __shared__ __align__(16) char dsm[];
    ulonglong2* wD = (ulonglong2*)(dsm + 65536);  // [256][8]: ((w0,w0),(w1,w1)) per j,colpair
    __shared__ float    gS[128][17];
    __shared__ int      lenS[128];
    __shared__ int      sMax;
    __shared__ unsigned sBase;

    const int tid  = threadIdx.x;
    const int cidx = blockIdx.x & 63;   // column tile
    const int bt   = blockIdx.x >> 6;   // batch tile
    const int b0   = bt * 128;
    const int hu0  = cidx * 4;

    if (tid == 0) { sMax = 0; sBase = *(volatile unsigned*)&g_bar_gen; }
    __syncthreads();
    atomicMax(&sMax, lengths[tid]);                 // tid covers full B=256
    if (tid < 128) lenS[tid] = lengths[b0 + tid];

    // w_hh slice: 16 gate cols x 256 j, stored as DUPLICATED pairs for f32x2
    for (int idx = tid; idx < HDIM * 16; idx += 256) {
        int j = idx >> 4, cc = idx & 15;
        int col = (cc >> 2) * HDIM + hu0 + (cc & 3);
        float w = w_hh[col * HDIM + j];
        float* wp = (float*)(wD + j * 8 + (cc >> 1));
        wp[2 * (cc & 1) + 0] = w;
        wp[2 * (cc & 1) + 1] = w;
    }
    // init c registers and h buffer 0 (transposed)
    const int pb = tid & 127;
    const int pu = tid >> 7;            // owns units pu, pu+2
    float creg0 = c0[(b0 + pb) * HDIM + hu0 + pu];
    float creg1 = c0[(b0 + pb) * HDIM + hu0 + pu + 2];
    for (int p = tid; p < 512; p += 256) {
        int b = p & 127, u = p >> 7;
        g_h[0][hu0 + u][b0 + b] = h0[(b0 + b) * HDIM + hu0 + u];
    }
    __syncthreads();
    const int      maxlen = sMax;
    const unsigned base   = sBase;
    grid_barrier(base + 1);                          // h[0] visible everywhere

    const int cp  = tid & 7;                         // gate-col pair (2cp, 2cp+1)
    const int q   = tid >> 3;                        // batch rows 4q..4q+3
    const int cc0 = 2 * cp;
    const int colpair = (cc0 >> 2) * HDIM + hu0 + (cc0 & 3);
    const unsigned hSaddr = (unsigned)__cvta_generic_to_shared(dsm);

    int cur = 0;
    for (int t = 0; t < maxlen; t++) {
        // ---- stage chunk 0 of h (j 0..63) into buf 0 via cp.async (.cg = L2, fresh) ----
#pragma unroll
        for (int r = 0; r < 8; r++) {
            int seg = tid + r * 256;
            int j = seg >> 5, bo = (seg & 31) << 2;
            cpa16(hSaddr + seg * 16, &g_h[cur][j][b0 + bo]);
        }
        asm volatile("cp.async.commit_group;");

        // ---- x-part: gather precomputed projection rows (long-latency, used at end) ----
        float2 xp0, xp1, xp2, xp3;
        {
            const int* ip = &inp[t * BATCH + b0 + 4 * q];
            xp0 = *(const float2*)&g_proj[(size_t)__ldg(ip+0) * G4H + colpair];
            xp1 = *(const float2*)&g_proj[(size_t)__ldg(ip+1) * G4H + colpair];
            xp2 = *(const float2*)&g_proj[(size_t)__ldg(ip+2) * G4H + colpair];
            xp3 = *(const float2*)&g_proj[(size_t)__ldg(ip+3) * G4H + colpair];
        }

        // ---- recurrent GEMM slice: packed f32x2 accumulators -----------------------
        unsigned long long a00 = 0ull, a01 = 0ull, a10 = 0ull, a11 = 0ull;
#pragma unroll
        for (int ch = 0; ch < 4; ch++) {
            if (ch < 3) {                            // prefetch next chunk
                int jb = (ch + 1) * 64, buf = (ch + 1) & 1;
#pragma unroll
                for (int r = 0; r < 8; r++) {
                    int seg = tid + r * 256;
                    int j = seg >> 5, bo = (seg & 31) << 2;
                    cpa16(hSaddr + buf * 32768 + seg * 16, &g_h[cur][jb + j][b0 + bo]);
                }
                asm volatile("cp.async.commit_group;");
                asm volatile("cp.async.wait_group 1;");
            } else {
                asm volatile("cp.async.wait_group 0;");
            }
            __syncthreads();                         // staged chunk visible CTA-wide
            const char* hb = dsm + (ch & 1) * 32768 + q * 16;
            const ulonglong2* wrow = wD + (ch * 64) * 8 + cp;
#pragma unroll 8
            for (int jj = 0; jj < 64; jj++) {
                ulonglong2 hv = *(const ulonglong2*)(hb + jj * 512);  // (b4q,b4q+1|b4q+2,b4q+3)
                ulonglong2 wv = wrow[jj * 8];                          // ((w0,w0)|(w1,w1))
                ffma2(a00, hv.x, wv.x); ffma2(a01, hv.x, wv.y);
                ffma2(a10, hv.y, wv.x); ffma2(a11, hv.y, wv.y);
            }
            __syncthreads();                         // done reading before buf reuse
        }

        // ---- unpack, add x-part, stage gates ---------------------------------------
        float2 f00 = unpk(a00), f01 = unpk(a01), f10 = unpk(a10), f11 = unpk(a11);
        gS[4*q+0][cc0] = f00.x + xp0.x;  gS[4*q+0][cc0+1] = f01.x + xp0.y;
        gS[4*q+1][cc0] = f00.y + xp1.x;  gS[4*q+1][cc0+1] = f01.y + xp1.y;
        gS[4*q+2][cc0] = f10.x + xp2.x;  gS[4*q+2][cc0+1] = f11.x + xp2.y;
        gS[4*q+3][cc0] = f10.y + xp3.x;  gS[4*q+3][cc0+1] = f11.y + xp3.y;
        __syncthreads();

        // ---- pointwise cell: this thread owns (pb, pu) and (pb, pu+2) --------------
        const int nxt = cur ^ 1;
        const int lastt = lenS[pb] - 1;
#pragma unroll
        for (int r = 0; r < 2; r++) {
            int u = pu + 2 * r;
            float gi = gS[pb][u],     gf = gS[pb][4 + u];
            float gc = gS[pb][8 + u], go = gS[pb][12 + u];
            float si = 1.0f / (1.0f + __expf(-gi));
            float sf = 1.0f / (1.0f + __expf(-gf));
            float so = 1.0f / (1.0f + __expf(-go));
            float tg = tanhf(gc);
            float cn = sf * (r ? creg1 : creg0) + si * tg;
            float hn = so * tanhf(cn);
            if (r) creg1 = cn; else creg0 = cn;
            int gb = b0 + pb, jj = hu0 + u;
            g_h[nxt][jj][gb] = hn;
            if (t == lastt) {
                g_lasth[gb][jj] = hn;
                if (wstate) {
                    out[ODIM*BATCH + gb*HDIM + jj] = hn;                 // last_h
                    out[ODIM*BATCH + BATCH*HDIM + gb*HDIM + jj] = cn;    // last_c
                }
            }
        }
        grid_barrier(base + 2 + t);
        cur = nxt;
    }
}

// ---------------- kernel 3: decoded = sigmoid(last_h @ dec_w^T) -------------
__global__ void __launch_bounds__(256) decode_kernel(
    const float* __restrict__ dec_w, float* __restrict__ out)
{
    int w = (blockIdx.x * blockDim.x + threadIdx.x) >> 5;   // global warp id
    int lane = threadIdx.x & 31;
    if (w >= BATCH * ODIM) return;
    int b = w >> 1, o = w & 1;
    float s = 0.0f;
#pragma unroll
    for (int j = lane; j < HDIM; j += 32) s += g_lasth[b][j] * dec_w[o * HDIM + j];
#pragma unroll
    for (int off = 16; off; off >>= 1) s += __shfl_xor_sync(0xFFFFFFFFu, s, off);
    if (lane == 0) out[b * ODIM + o] = 1.0f / (1.0f + __expf(-s));
}

// ---------------- launcher --------------------------------------------------
extern "C" void kernel_launch(void* const* d_in, const int* in_sizes, int n_in,
                              void* d_out, int out_size) {
    const int*   inp     = (const int*)  d_in[0];
    const int*   lengths = (const int*)  d_in[1];
    const float* h0      = (const float*)d_in[2];
    const float* c0      = (const float*)d_in[3];
    const float* emb     = (const float*)d_in[4];
    const float* w_ih    = (const float*)d_in[5];
    const float* w_hh    = (const float*)d_in[6];
    const float* b_ih    = (const float*)d_in[7];
    const float* b_hh    = (const float*)d_in[8];
    const float* dec_w   = (const float*)d_in[9];
    float* out = (float*)d_out;
    int wstate = (out_size >= ODIM * BATCH + 2 * BATCH * HDIM) ? 1 : 0;

    cudaFuncSetAttribute(lstm_kernel, cudaFuncAttributeMaxDynamicSharedMemorySize, DSMEM);

    prep_proj_kernel<<<500 * 16, 256>>>(emb, w_ih, b_ih, b_hh);
    lstm_kernel<<<NCTA, 256, DSMEM>>>(inp, lengths, h0, c0, w_hh, out, wstate);
    decode_kernel<<<64, 256>>>(dec_w, out);
}

// round 12
// speedup vs baseline: 4.4517x; 1.2176x over previous
#include <cuda_runtime.h>

#define BATCH 256
#define EDIM  128
#define HDIM  256
#define VOCAB 32000
#define G4H   1024   // 4*H
#define ODIM  2
#define NCTA  128    // 8 batch-tiles x 16 unit-tiles; <=148 SMs -> wave-1 co-resident
#define DSMEM (32768 + 131072)  // hS 2-chunk (2x16KB) + duplicated w_hh (128KB)

// ---------------- scratch (device globals; no runtime allocation) -----------
__device__ float    g_proj[(size_t)VOCAB * G4H];  // emb@w_ih^T + bias  (131 MB)
__device__ float    g_h[2][HDIM][BATCH];          // double-buffered h, TRANSPOSED [j][b]
__device__ float    g_lasth[BATCH][HDIM];         // last valid h (for decode)
__device__ unsigned g_bar_gen;                    // grid-barrier generation (monotonic)
__device__ unsigned g_bar_count;                  // grid-barrier arrival counter

// ---------------- asm helpers ------------------------------------------------
__device__ __forceinline__ void ffma2(unsigned long long& d,
                                      unsigned long long a, unsigned long long b) {
    asm("fma.rn.f32x2 %0, %1, %2, %0;" : "+l"(d) : "l"(a), "l"(b));
}
__device__ __forceinline__ float2 unpk(unsigned long long v) {
    float2 r; asm("mov.b64 {%0,%1}, %2;" : "=f"(r.x), "=f"(r.y) : "l"(v)); return r;
}
__device__ __forceinline__ void cpa16(unsigned dst, const void* src) {
    asm volatile("cp.async.cg.shared.global [%0], [%1], 16;" :: "r"(dst), "l"(src));
}
__device__ __forceinline__ unsigned atom_add_acqrel(unsigned* p) {
    unsigned old;
    asm volatile("atom.acq_rel.gpu.global.add.u32 %0, [%1], 1;"
                 : "=r"(old) : "l"(p) : "memory");
    return old;
}
__device__ __forceinline__ void st_release(unsigned* p, unsigned v) {
    asm volatile("st.release.gpu.global.u32 [%0], %1;" :: "l"(p), "r"(v) : "memory");
}
__device__ __forceinline__ unsigned ld_acquire(unsigned* p) {
    unsigned v;
    asm volatile("ld.acquire.gpu.global.u32 %0, [%1];" : "=r"(v) : "l"(p) : "memory");
    return v;
}

// ---------------- grid barrier (monotonic target; acq/rel, replay-safe) -----
__device__ __forceinline__ void grid_barrier(unsigned target) {
    __syncthreads();
    if (threadIdx.x == 0) {
        unsigned arrived = atom_add_acqrel(&g_bar_count);   // release my writes
        if (arrived == NCTA - 1) {
            g_bar_count = 0u;                               // ordered by release below
            st_release(&g_bar_gen, target);
        } else {
            while ((int)(ld_acquire(&g_bar_gen) - target) < 0) { }
        }
    }
    __syncthreads();
}

// ---------------- kernel 1: proj_table = emb @ w_ih^T + (b_ih + b_hh) -------
__global__ void __launch_bounds__(256) prep_proj_kernel(
    const float* __restrict__ emb, const float* __restrict__ w_ih,
    const float* __restrict__ b_ih, const float* __restrict__ b_hh)
{
    __shared__ float sA[64][65];   // sA[k][v]
    __shared__ float sW[64][65];   // sW[k][c]
    const int cb = blockIdx.x & 15, vb = blockIdx.x >> 4;
    const int vbase = vb * 64, cbase = cb * 64;
    const int tid = threadIdx.x;
    const int c0 = (tid & 15) * 4, v0 = (tid >> 4) * 4;

    float acc[4][4];
#pragma unroll
    for (int i = 0; i < 4; i++)
#pragma unroll
        for (int j = 0; j < 4; j++) acc[i][j] = 0.0f;

    for (int kc = 0; kc < EDIM; kc += 64) {
#pragma unroll
        for (int r = 0; r < 16; r++) {
            int idx = tid + r * 256;
            int row = idx >> 6, kk = idx & 63;
            sA[kk][row] = emb [(vbase + row) * EDIM + kc + kk];
            sW[kk][row] = w_ih[(cbase + row) * EDIM + kc + kk];
        }
        __syncthreads();
#pragma unroll 8
        for (int k = 0; k < 64; k++) {
            float a0 = sA[k][v0], a1 = sA[k][v0+1], a2 = sA[k][v0+2], a3 = sA[k][v0+3];
            float w0 = sW[k][c0], w1 = sW[k][c0+1], w2 = sW[k][c0+2], w3 = sW[k][c0+3];
            acc[0][0]+=a0*w0; acc[0][1]+=a0*w1; acc[0][2]+=a0*w2; acc[0][3]+=a0*w3;
            acc[1][0]+=a1*w0; acc[1][1]+=a1*w1; acc[1][2]+=a1*w2; acc[1][3]+=a1*w3;
            acc[2][0]+=a2*w0; acc[2][1]+=a2*w1; acc[2][2]+=a2*w2; acc[2][3]+=a2*w3;
            acc[3][0]+=a3*w0; acc[3][1]+=a3*w1; acc[3][2]+=a3*w2; acc[3][3]+=a3*w3;
        }
        __syncthreads();
    }
    float bias[4];
#pragma unroll
    for (int j = 0; j < 4; j++) bias[j] = b_ih[cbase + c0 + j] + b_hh[cbase + c0 + j];
#pragma unroll
    for (int i = 0; i < 4; i++) {
        float4 v = make_float4(acc[i][0]+bias[0], acc[i][1]+bias[1],
                               acc[i][2]+bias[2], acc[i][3]+bias[3]);
        *(float4*)&g_proj[(size_t)(vbase + v0 + i) * G4H + cbase + c0] = v;
    }
}

// ---------------- kernel 2: persistent LSTM recurrence ----------------------
// 128 CTAs = 8 batch tiles (32 b) x 16 unit tiles (16 hidden units = 64 gate cols)
__global__ void __launch_bounds__(256) lstm_kernel(
    const int*   __restrict__ inp,      // [S, B] time-major
    const int*   __restrict__ lengths,  // [B]
    const float* __restrict__ h0,       // [1, B, H]
    const float* __restrict__ c0,       // [1, B, H]
    const float* __restrict__ w_hh,     // [4H, H]
    float*       __restrict__ out,      // decoded(512) | last_h(65536) | last_c(65536)
    int wstate)
{
    extern __shared__ __align__(16) char dsm[];
    // dsm[0..32768): hS[2][128][32] floats (2 chunks of 128 j x 32 b)
    // dsm[32768..):  wD[256][32] ulonglong2 = ((w0,w0),(w1,w1)) per (j, colpair)
    ulonglong2* wD = (ulonglong2*)(dsm + 32768);
    __shared__ float    gS[32][65];     // gates [b_local][gate*16+unit]
    __shared__ int      lenS[32];
    __shared__ int      sMax;
    __shared__ unsigned sBase;

    const int tid = threadIdx.x;
    const int ut  = blockIdx.x & 15;    // unit tile
    const int bt  = blockIdx.x >> 4;    // batch tile
    const int b0  = bt * 32;
    const int hu0 = ut * 16;

    if (tid == 0) { sMax = 0; sBase = *(volatile unsigned*)&g_bar_gen; }
    __syncthreads();
    atomicMax(&sMax, lengths[tid]);                 // tid covers full B=256
    if (tid < 32) lenS[tid] = lengths[b0 + tid];

    // w_hh slice: 64 gate cols (= 16 units x 4 gates) x 256 j, DUPLICATED pairs
    for (int idx = tid; idx < HDIM * 32; idx += 256) {
        int P2 = idx & 31, j = idx >> 5;
        int cc = 2 * P2;
        int col = (cc >> 4) * HDIM + hu0 + (cc & 15);
        float w0 = w_hh[col * HDIM + j];
        float w1 = w_hh[(col + 1) * HDIM + j];
        float* wp = (float*)&wD[j * 32 + P2];
        wp[0] = w0; wp[1] = w0; wp[2] = w1; wp[3] = w1;
    }
    // init c registers and h buffer 0 (transposed)
    const int pb = tid & 31;            // pointwise batch row
    const int pu = tid >> 5;            // owns units pu, pu+8
    float creg0 = c0[(b0 + pb) * HDIM + hu0 + pu];
    float creg1 = c0[(b0 + pb) * HDIM + hu0 + pu + 8];
    for (int p = tid; p < 512; p += 256) {
        int b = p & 31, u = p >> 5;
        g_h[0][hu0 + u][b0 + b] = h0[(b0 + b) * HDIM + hu0 + u];
    }
    __syncthreads();
    const int      maxlen = sMax;
    const unsigned base   = sBase;
    grid_barrier(base + 1);                          // h[0] visible everywhere

    // GEMM thread mapping: warp w (tid>>5), lane l (tid&31)
    //   qq = l>>2  : batch quad (4 rows 4qq..4qq+3) -> 8 distinct hv per warp
    //   P  = w*4 + (l&3) : colpair (cols 2P, 2P+1)  -> 4 distinct wv per warp
    const int qq  = (tid & 31) >> 2;
    const int P   = (tid >> 5) * 4 + (tid & 3);
    const int cc0 = 2 * P;
    const int colpair = (cc0 >> 4) * HDIM + hu0 + (cc0 & 15);
    const unsigned hSaddr = (unsigned)__cvta_generic_to_shared(dsm);

    int cur = 0;
    for (int t = 0; t < maxlen; t++) {
        // ---- stage both h chunks (32 KB total) via cp.async.cg (L2, fresh) ----
#pragma unroll
        for (int ch = 0; ch < 2; ch++) {
#pragma unroll
            for (int r = 0; r < 4; r++) {
                int s = tid + r * 256;               // seg within chunk (1024 segs)
                int j = ch * 128 + (s >> 3);
                int bo = (s & 7) * 4;
                cpa16(hSaddr + ch * 16384 + s * 16, &g_h[cur][j][b0 + bo]);
            }
            asm volatile("cp.async.commit_group;");
        }

        // ---- x-part: gather precomputed projection rows (used at the end) ----
        float2 xp0, xp1, xp2, xp3;
        {
            const int* ip = &inp[t * BATCH + b0 + 4 * qq];
            xp0 = *(const float2*)&g_proj[(size_t)__ldg(ip+0) * G4H + colpair];
            xp1 = *(const float2*)&g_proj[(size_t)__ldg(ip+1) * G4H + colpair];
            xp2 = *(const float2*)&g_proj[(size_t)__ldg(ip+2) * G4H + colpair];
            xp3 = *(const float2*)&g_proj[(size_t)__ldg(ip+3) * G4H + colpair];
        }

        // ---- recurrent GEMM slice: packed f32x2 accumulators ------------------
        unsigned long long a00 = 0ull, a01 = 0ull, a10 = 0ull, a11 = 0ull;
        asm volatile("cp.async.wait_group 1;");
        __syncthreads();                             // chunk 0 visible CTA-wide
#pragma unroll
        for (int ch = 0; ch < 2; ch++) {
            const char* hb = dsm + ch * 16384 + qq * 16;
            const ulonglong2* wrow = wD + (ch * 128) * 32 + P;
#pragma unroll 16
            for (int jj = 0; jj < 128; jj++) {
                ulonglong2 hv = *(const ulonglong2*)(hb + jj * 128); // (b0..b1|b2..b3)
                ulonglong2 wv = wrow[jj * 32];                        // ((w0,w0)|(w1,w1))
                ffma2(a00, hv.x, wv.x); ffma2(a01, hv.x, wv.y);
                ffma2(a10, hv.y, wv.x); ffma2(a11, hv.y, wv.y);
            }
            if (ch == 0) {
                asm volatile("cp.async.wait_group 0;");
                __syncthreads();                     // chunk 1 visible CTA-wide
            }
        }

        // ---- unpack, add x-part, stage gates ---------------------------------
        float2 f00 = unpk(a00), f01 = unpk(a01), f10 = unpk(a10), f11 = unpk(a11);
        gS[4*qq+0][cc0] = f00.x + xp0.x;  gS[4*qq+0][cc0+1] = f01.x + xp0.y;
        gS[4*qq+1][cc0] = f00.y + xp1.x;  gS[4*qq+1][cc0+1] = f01.y + xp1.y;
        gS[4*qq+2][cc0] = f10.x + xp2.x;  gS[4*qq+2][cc0+1] = f11.x + xp2.y;
        gS[4*qq+3][cc0] = f10.y + xp3.x;  gS[4*qq+3][cc0+1] = f11.y + xp3.y;
        __syncthreads();

        // ---- pointwise cell: this thread owns (pb, pu) and (pb, pu+8) --------
        const int nxt = cur ^ 1;
        const int lastt = lenS[pb] - 1;
#pragma unroll
        for (int r = 0; r < 2; r++) {
            int u = pu + 8 * r;
            float gi = gS[pb][u],      gf = gS[pb][16 + u];
            float gc = gS[pb][32 + u], go = gS[pb][48 + u];
            float si = 1.0f / (1.0f + __expf(-gi));
            float sf = 1.0f / (1.0f + __expf(-gf));
            float so = 1.0f / (1.0f + __expf(-go));
            float tg = tanhf(gc);
            float cn = sf * (r ? creg1 : creg0) + si * tg;
            float hn = so * tanhf(cn);
            if (r) creg1 = cn; else creg0 = cn;
            int gb = b0 + pb, jj = hu0 + u;
            g_h[nxt][jj][gb] = hn;
            if (t == lastt) {
                g_lasth[gb][jj] = hn;
                if (wstate) {
                    out[ODIM*BATCH + gb*HDIM + jj] = hn;                 // last_h
                    out[ODIM*BATCH + BATCH*HDIM + gb*HDIM + jj] = cn;    // last_c
                }
            }
        }
        grid_barrier(base + 2 + t);
        cur = nxt;
    }
}

// ---------------- kernel 3: decoded = sigmoid(last_h @ dec_w^T) -------------
__global__ void __launch_bounds__(256) decode_kernel(
    const float* __restrict__ dec_w, float* __restrict__ out)
{
    int w = (blockIdx.x * blockDim.x + threadIdx.x) >> 5;   // global warp id
    int lane = threadIdx.x & 31;
    if (w >= BATCH * ODIM) return;
    int b = w >> 1, o = w & 1;
    float s = 0.0f;
#pragma unroll
    for (int j = lane; j < HDIM; j += 32) s += g_lasth[b][j] * dec_w[o * HDIM + j];
#pragma unroll
    for (int off = 16; off; off >>= 1) s += __shfl_xor_sync(0xFFFFFFFFu, s, off);
    if (lane == 0) out[b * ODIM + o] = 1.0f / (1.0f + __expf(-s));
}

// ---------------- launcher --------------------------------------------------
extern "C" void kernel_launch(void* const* d_in, const int* in_sizes, int n_in,
                              void* d_out, int out_size) {
    const int*   inp     = (const int*)  d_in[0];
    const int*   lengths = (const int*)  d_in[1];
    const float* h0      = (const float*)d_in[2];
    const float* c0      = (const float*)d_in[3];
    const float* emb     = (const float*)d_in[4];
    const float* w_ih    = (const float*)d_in[5];
    const float* w_hh    = (const float*)d_in[6];
    const float* b_ih    = (const float*)d_in[7];
    const float* b_hh    = (const float*)d_in[8];
    const float* dec_w   = (const float*)d_in[9];
    float* out = (float*)d_out;
    int wstate = (out_size >= ODIM * BATCH + 2 * BATCH * HDIM) ? 1 : 0;

    cudaFuncSetAttribute(lstm_kernel, cudaFuncAttributeMaxDynamicSharedMemorySize, DSMEM);

    prep_proj_kernel<<<500 * 16, 256>>>(emb, w_ih, b_ih, b_hh);
    lstm_kernel<<<NCTA, 256, DSMEM>>>(inp, lengths, h0, c0, w_hh, out, wstate);
    decode_kernel<<<64, 256>>>(dec_w, out);
}

// round 13
// speedup vs baseline: 4.7287x; 1.0622x over previous
#include <cuda_runtime.h>

#define BATCH 256
#define EDIM  128
#define HDIM  256
#define VOCAB 32000
#define G4H   1024   // 4*H
#define ODIM  2
#define NCTA  128    // 8 batch-tiles x 16 unit-tiles; <=148 SMs -> wave-1 co-resident
#define DSMEM (32768 + 65536)   // hS[256][32] + wW plain pairs [8][256][2x ull2]

// ---------------- scratch (device globals; no runtime allocation) -----------
__device__ float    g_proj[(size_t)VOCAB * G4H];  // emb@w_ih^T + bias  (131 MB)
__device__ float    g_h[2][HDIM][BATCH];          // double-buffered h, TRANSPOSED [j][b]
__device__ float    g_lasth[BATCH][HDIM];         // last valid h (for decode)
__device__ unsigned g_bar_gen;                    // grid-barrier generation (monotonic)
__device__ unsigned g_bar_count;                  // grid-barrier arrival counter

// ---------------- asm helpers ------------------------------------------------
__device__ __forceinline__ void ffma2(unsigned long long& d,
                                      unsigned long long a, unsigned long long b) {
    asm("fma.rn.f32x2 %0, %1, %2, %0;" : "+l"(d) : "l"(a), "l"(b));
}
__device__ __forceinline__ float2 unpk(unsigned long long v) {
    float2 r; asm("mov.b64 {%0,%1}, %2;" : "=f"(r.x), "=f"(r.y) : "l"(v)); return r;
}
__device__ __forceinline__ unsigned long long dup2(float x) {
    unsigned long long r; asm("mov.b64 %0, {%1,%1};" : "=l"(r) : "f"(x)); return r;
}
__device__ __forceinline__ void cpa16(unsigned dst, const void* src) {
    asm volatile("cp.async.cg.shared.global [%0], [%1], 16;" :: "r"(dst), "l"(src));
}
__device__ __forceinline__ unsigned atom_add_acqrel(unsigned* p) {
    unsigned old;
    asm volatile("atom.acq_rel.gpu.global.add.u32 %0, [%1], 1;"
                 : "=r"(old) : "l"(p) : "memory");
    return old;
}
__device__ __forceinline__ void st_release(unsigned* p, unsigned v) {
    asm volatile("st.release.gpu.global.u32 [%0], %1;" :: "l"(p), "r"(v) : "memory");
}
__device__ __forceinline__ unsigned ld_acquire(unsigned* p) {
    unsigned v;
    asm volatile("ld.acquire.gpu.global.u32 %0, [%1];" : "=r"(v) : "l"(p) : "memory");
    return v;
}

// ---------------- grid barrier (monotonic target; acq/rel, replay-safe) -----
__device__ __forceinline__ void grid_barrier(unsigned target) {
    __syncthreads();
    if (threadIdx.x == 0) {
        unsigned arrived = atom_add_acqrel(&g_bar_count);   // release my writes
        if (arrived == NCTA - 1) {
            g_bar_count = 0u;
            st_release(&g_bar_gen, target);
        } else {
            while ((int)(ld_acquire(&g_bar_gen) - target) < 0) { }
        }
    }
    __syncthreads();
}

// ---------------- kernel 1: proj_table = emb @ w_ih^T + (b_ih + b_hh) -------
__global__ void __launch_bounds__(256) prep_proj_kernel(
    const float* __restrict__ emb, const float* __restrict__ w_ih,
    const float* __restrict__ b_ih, const float* __restrict__ b_hh)
{
    __shared__ float sA[64][65];   // sA[k][v]
    __shared__ float sW[64][65];   // sW[k][c]
    const int cb = blockIdx.x & 15, vb = blockIdx.x >> 4;
    const int vbase = vb * 64, cbase = cb * 64;
    const int tid = threadIdx.x;
    const int c0 = (tid & 15) * 4, v0 = (tid >> 4) * 4;

    float acc[4][4];
#pragma unroll
    for (int i = 0; i < 4; i++)
#pragma unroll
        for (int j = 0; j < 4; j++) acc[i][j] = 0.0f;

    for (int kc = 0; kc < EDIM; kc += 64) {
#pragma unroll
        for (int r = 0; r < 16; r++) {
            int idx = tid + r * 256;
            int row = idx >> 6, kk = idx & 63;
            sA[kk][row] = emb [(vbase + row) * EDIM + kc + kk];
            sW[kk][row] = w_ih[(cbase + row) * EDIM + kc + kk];
        }
        __syncthreads();
#pragma unroll 8
        for (int k = 0; k < 64; k++) {
            float a0 = sA[k][v0], a1 = sA[k][v0+1], a2 = sA[k][v0+2], a3 = sA[k][v0+3];
            float w0 = sW[k][c0], w1 = sW[k][c0+1], w2 = sW[k][c0+2], w3 = sW[k][c0+3];
            acc[0][0]+=a0*w0; acc[0][1]+=a0*w1; acc[0][2]+=a0*w2; acc[0][3]+=a0*w3;
            acc[1][0]+=a1*w0; acc[1][1]+=a1*w1; acc[1][2]+=a1*w2; acc[1][3]+=a1*w3;
            acc[2][0]+=a2*w0; acc[2][1]+=a2*w1; acc[2][2]+=a2*w2; acc[2][3]+=a2*w3;
            acc[3][0]+=a3*w0; acc[3][1]+=a3*w1; acc[3][2]+=a3*w2; acc[3][3]+=a3*w3;
        }
        __syncthreads();
    }
    float bias[4];
#pragma unroll
    for (int j = 0; j < 4; j++) bias[j] = b_ih[cbase + c0 + j] + b_hh[cbase + c0 + j];
#pragma unroll
    for (int i = 0; i < 4; i++) {
        float4 v = make_float4(acc[i][0]+bias[0], acc[i][1]+bias[1],
                               acc[i][2]+bias[2], acc[i][3]+bias[3]);
        *(float4*)&g_proj[(size_t)(vbase + v0 + i) * G4H + cbase + c0] = v;
    }
}

// ---------------- kernel 2: persistent LSTM recurrence ----------------------
// 128 CTAs = 8 batch tiles (32 b) x 16 unit tiles (16 units = 64 gate cols).
// lane = batch row (LDS.32 h, 1 crossbar phase); warp owns 8 gate cols with
// warp-uniform w (broadcast LDS.128, plain pairs); packed fma.rn.f32x2 core.
__global__ void __launch_bounds__(256) lstm_kernel(
    const int*   __restrict__ inp,      // [S, B] time-major
    const int*   __restrict__ lengths,  // [B]
    const float* __restrict__ h0,       // [1, B, H]
    const float* __restrict__ c0,       // [1, B, H]
    const float* __restrict__ w_hh,     // [4H, H]
    float*       __restrict__ out,      // decoded(512) | last_h(65536) | last_c(65536)
    int wstate)
{
    extern __shared__ __align__(16) char dsm[];
    float*      hS = (float*)dsm;                  // [256][32] staged h
    ulonglong2* wW = (ulonglong2*)(dsm + 32768);   // [8 warps][256 j][2]: plain (wc,wc+1) pairs
    __shared__ float    gS[32][65];                // gates [b_local][g*16+u]
    __shared__ int      lenS[32];
    __shared__ int      sMax;
    __shared__ unsigned sBase;

    const int tid  = threadIdx.x;
    const int wid  = tid >> 5;
    const int lane = tid & 31;
    const int ut   = blockIdx.x & 15;   // unit tile
    const int bt   = blockIdx.x >> 4;   // batch tile
    const int b0   = bt * 32;
    const int hu0  = ut * 16;

    if (tid == 0) { sMax = 0; sBase = *(volatile unsigned*)&g_bar_gen; }
    __syncthreads();
    atomicMax(&sMax, lengths[tid]);                 // tid covers full B=256
    if (tid < 32) lenS[tid] = lengths[b0 + tid];

    // fill wW: 8192 plain pairs (w[c], w[c+1]); float offset (w*256+j)*8 + 2k
    {
        float* wf = (float*)wW;
        for (int p = tid; p < 8192; p += 256) {
            int w_ = p >> 10, rem = p & 1023, j = rem >> 2, k = rem & 3;
            int c  = 8 * w_ + 2 * k;
            int gc = (c >> 4) * HDIM + hu0 + (c & 15);
            wf[(w_ * 256 + j) * 8 + 2 * k    ] = w_hh[gc * HDIM + j];
            wf[(w_ * 256 + j) * 8 + 2 * k + 1] = w_hh[(gc + 1) * HDIM + j];
        }
    }
    // init c registers and h buffer 0 (transposed)
    const int pb = tid & 31;            // pointwise batch row
    const int pu = tid >> 5;            // owns units pu, pu+8
    float creg0 = c0[(b0 + pb) * HDIM + hu0 + pu];
    float creg1 = c0[(b0 + pb) * HDIM + hu0 + pu + 8];
    for (int p = tid; p < 512; p += 256) {
        int b = p & 31, u = p >> 5;
        g_h[0][hu0 + u][b0 + b] = h0[(b0 + b) * HDIM + hu0 + u];
    }
    __syncthreads();
    const int      maxlen = sMax;
    const unsigned base   = sBase;

    // proj row base for this thread's 8 contiguous gate cols (same gate block)
    const int pcol = ((8 * wid) >> 4) * HDIM + hu0 + ((8 * wid) & 15);
    const unsigned hSaddr = (unsigned)__cvta_generic_to_shared(dsm);

    // prefetch x-part for t=0 (1 token per lane; 2 contiguous float4)
    float4 xq0, xq1;
    {
        int tok = __ldg(&inp[0 * BATCH + b0 + lane]);
        const float* pr = &g_proj[(size_t)tok * G4H + pcol];
        xq0 = *(const float4*)pr;  xq1 = *(const float4*)(pr + 4);
    }
    grid_barrier(base + 1);                          // h[0] visible everywhere

    int cur = 0;
    for (int t = 0; t < maxlen; t++) {
        // ---- stage h[cur] (32 KB) in 2 chunks via cp.async.cg (L2, fresh) ----
#pragma unroll
        for (int ch = 0; ch < 2; ch++) {
#pragma unroll
            for (int r = 0; r < 4; r++) {
                int s = tid + r * 256;               // seg in chunk (1024 segs x 16B)
                int j = ch * 128 + (s >> 3);
                int bo = (s & 7) * 4;
                cpa16(hSaddr + ch * 16384 + s * 16, &g_h[cur][j][b0 + bo]);
            }
            asm volatile("cp.async.commit_group;");
        }

        // ---- recurrent GEMM: lane=batch, warp-uniform w, f32x2 core ----------
        unsigned long long a0 = 0ull, a1 = 0ull, a2 = 0ull, a3 = 0ull;
        asm volatile("cp.async.wait_group 1;");
        __syncthreads();                             // chunk 0 visible
#pragma unroll
        for (int ch = 0; ch < 2; ch++) {
            const float*      hp = hS + ch * 128 * 32 + lane;
            const ulonglong2* wp = wW + (wid * 256 + ch * 128) * 2;
#pragma unroll 8
            for (int jj = 0; jj < 128; jj++) {
                unsigned long long h2 = dup2(hp[jj * 32]);   // LDS.32 + mov.b64
                ulonglong2 wa = wp[jj * 2];                  // bcast LDS.128 (cols +0..3)
                ulonglong2 wb = wp[jj * 2 + 1];              // bcast LDS.128 (cols +4..7)
                ffma2(a0, h2, wa.x); ffma2(a1, h2, wa.y);
                ffma2(a2, h2, wb.x); ffma2(a3, h2, wb.y);
            }
            if (ch == 0) {
                asm volatile("cp.async.wait_group 0;");
                __syncthreads();                     // chunk 1 visible
            }
        }

        // ---- add x-part, stage gates (conflict-free: bank = lane) ------------
        {
            float2 f0 = unpk(a0), f1 = unpk(a1), f2 = unpk(a2), f3 = unpk(a3);
            float* g = &gS[lane][8 * wid];
            g[0] = f0.x + xq0.x;  g[1] = f0.y + xq0.y;
            g[2] = f1.x + xq0.z;  g[3] = f1.y + xq0.w;
            g[4] = f2.x + xq1.x;  g[5] = f2.y + xq1.y;
            g[6] = f3.x + xq1.z;  g[7] = f3.y + xq1.w;
        }
        __syncthreads();

        // ---- pointwise cell: this thread owns (pb, pu) and (pb, pu+8) --------
        const int nxt = cur ^ 1;
        const int lastt = lenS[pb] - 1;
#pragma unroll
        for (int r = 0; r < 2; r++) {
            int u = pu + 8 * r;
            float gi = gS[pb][u],      gf = gS[pb][16 + u];
            float gc = gS[pb][32 + u], go = gS[pb][48 + u];
            float si = 1.0f / (1.0f + __expf(-gi));
            float sf = 1.0f / (1.0f + __expf(-gf));
            float so = 1.0f / (1.0f + __expf(-go));
            float tg = tanhf(gc);
            float cn = sf * (r ? creg1 : creg0) + si * tg;
            float hn = so * tanhf(cn);
            if (r) creg1 = cn; else creg0 = cn;
            int gb = b0 + pb, jj = hu0 + u;
            g_h[nxt][jj][gb] = hn;
            if (t == lastt) {
                g_lasth[gb][jj] = hn;
                if (wstate) {
                    out[ODIM*BATCH + gb*HDIM + jj] = hn;                 // last_h
                    out[ODIM*BATCH + BATCH*HDIM + gb*HDIM + jj] = cn;    // last_c
                }
            }
        }

        // ---- prefetch next step's x-part (overlaps barrier wait) -------------
        if (t + 1 < maxlen) {
            int tok = __ldg(&inp[(t + 1) * BATCH + b0 + lane]);
            const float* pr = &g_proj[(size_t)tok * G4H + pcol];
            xq0 = *(const float4*)pr;  xq1 = *(const float4*)(pr + 4);
        }
        grid_barrier(base + 2 + t);
        cur = nxt;
    }
}

// ---------------- kernel 3: decoded = sigmoid(last_h @ dec_w^T) -------------
__global__ void __launch_bounds__(256) decode_kernel(
    const float* __restrict__ dec_w, float* __restrict__ out)
{
    int w = (blockIdx.x * blockDim.x + threadIdx.x) >> 5;   // global warp id
    int lane = threadIdx.x & 31;
    if (w >= BATCH * ODIM) return;
    int b = w >> 1, o = w & 1;
    float s = 0.0f;
#pragma unroll
    for (int j = lane; j < HDIM; j += 32) s += g_lasth[b][j] * dec_w[o * HDIM + j];
#pragma unroll
    for (int off = 16; off; off >>= 1) s += __shfl_xor_sync(0xFFFFFFFFu, s, off);
    if (lane == 0) out[b * ODIM + o] = 1.0f / (1.0f + __expf(-s));
}

// ---------------- launcher --------------------------------------------------
extern "C" void kernel_launch(void* const* d_in, const int* in_sizes, int n_in,
                              void* d_out, int out_size) {
    const int*   inp     = (const int*)  d_in[0];
    const int*   lengths = (const int*)  d_in[1];
    const float* h0      = (const float*)d_in[2];
    const float* c0      = (const float*)d_in[3];
    const float* emb     = (const float*)d_in[4];
    const float* w_ih    = (const float*)d_in[5];
    const float* w_hh    = (const float*)d_in[6];
    const float* b_ih    = (const float*)d_in[7];
    const float* b_hh    = (const float*)d_in[8];
    const float* dec_w   = (const float*)d_in[9];
    float* out = (float*)d_out;
    int wstate = (out_size >= ODIM * BATCH + 2 * BATCH * HDIM) ? 1 : 0;

    cudaFuncSetAttribute(lstm_kernel, cudaFuncAttributeMaxDynamicSharedMemorySize, DSMEM);

    prep_proj_kernel<<<500 * 16, 256>>>(emb, w_ih, b_ih, b_hh);
    lstm_kernel<<<NCTA, 256, DSMEM>>>(inp, lengths, h0, c0, w_hh, out, wstate);
    decode_kernel<<<64, 256>>>(dec_w, out);
}